// round 1
// baseline (speedup 1.0000x reference)
#include <cuda_runtime.h>

#define SEQ 4096
#define EMB 1024
#define NH  16
#define HD  64
#define QKVN (3*EMB)

// Scratch (no cudaMalloc allowed): qkv projection [S, 3E], attention output [S, E]
__device__ float g_qkv[(size_t)SEQ * QKVN];
__device__ float g_att[(size_t)SEQ * EMB];

// ---------------------------------------------------------------------------
// SGEMM: C[M,N] = A[M,K] @ B[N,K]^T + bias[N]
// 128x128 block tile, BK=16, 256 threads, 8x8 register micro-tile.
// ---------------------------------------------------------------------------
__global__ __launch_bounds__(256)
void sgemm_bias(const float* __restrict__ A, const float* __restrict__ B,
                const float* __restrict__ bias, float* __restrict__ C,
                int M, int N, int K)
{
    const int BK = 16;
    __shared__ float As[16][132];
    __shared__ float Bs[16][132];

    int t  = threadIdx.x;
    int tx = t & 15;        // 0..15 -> output cols tx*8..tx*8+7
    int ty = t >> 4;        // 0..15 -> output rows ty*8..ty*8+7
    int bm = blockIdx.y * 128;
    int bn = blockIdx.x * 128;

    const float* Ab = A + (size_t)bm * K;
    const float* Bb = B + (size_t)bn * K;

    int lm = t >> 2;          // 0..63 row within load pass
    int lk = (t & 3) << 2;    // k offset 0,4,8,12

    float acc[8][8];
#pragma unroll
    for (int i = 0; i < 8; i++)
#pragma unroll
        for (int j = 0; j < 8; j++) acc[i][j] = 0.f;

    for (int k0 = 0; k0 < K; k0 += BK) {
#pragma unroll
        for (int p = 0; p < 2; p++) {
            int m = lm + p * 64;
            float4 va = *(const float4*)(Ab + (size_t)m * K + k0 + lk);
            As[lk + 0][m] = va.x; As[lk + 1][m] = va.y;
            As[lk + 2][m] = va.z; As[lk + 3][m] = va.w;
            float4 vb = *(const float4*)(Bb + (size_t)m * K + k0 + lk);
            Bs[lk + 0][m] = vb.x; Bs[lk + 1][m] = vb.y;
            Bs[lk + 2][m] = vb.z; Bs[lk + 3][m] = vb.w;
        }
        __syncthreads();

#pragma unroll
        for (int k = 0; k < BK; k++) {
            float a[8], b[8];
            *(float4*)&a[0] = *(const float4*)&As[k][ty * 8];
            *(float4*)&a[4] = *(const float4*)&As[k][ty * 8 + 4];
            *(float4*)&b[0] = *(const float4*)&Bs[k][tx * 8];
            *(float4*)&b[4] = *(const float4*)&Bs[k][tx * 8 + 4];
#pragma unroll
            for (int i = 0; i < 8; i++)
#pragma unroll
                for (int j = 0; j < 8; j++)
                    acc[i][j] = fmaf(a[i], b[j], acc[i][j]);
        }
        __syncthreads();
    }

#pragma unroll
    for (int i = 0; i < 8; i++) {
        int m = bm + ty * 8 + i;
        float* Crow = C + (size_t)m * N + bn + tx * 8;
        const float* brow = bias + bn + tx * 8;
#pragma unroll
        for (int j = 0; j < 8; j += 4) {
            float4 v;
            v.x = acc[i][j + 0] + brow[j + 0];
            v.y = acc[i][j + 1] + brow[j + 1];
            v.z = acc[i][j + 2] + brow[j + 2];
            v.w = acc[i][j + 3] + brow[j + 3];
            *(float4*)(Crow + j) = v;
        }
    }
}

// ---------------------------------------------------------------------------
// Flash attention (fp32, online softmax).
// Block: 64 query rows of one head, 256 threads.
// Thread (r = t/4, g = t%4) owns: QK logits cols g*16..g*16+15 of row r,
// and output dims g*16..g*16+15 of row r.
// qkv layout: row s -> [h*192 + d] = q, [h*192+64+d] = k, [h*192+128+d] = v.
// ---------------------------------------------------------------------------
__global__ __launch_bounds__(256)
void attn_kernel()
{
    extern __shared__ float smbuf[];
    float* QP = smbuf;              // 64*68 floats: Q staging, then P (probs)
    float* Ks = smbuf + 64 * 68;    // 64*64
    float* Vs = Ks + 64 * 64;       // 64*64

    int h  = blockIdx.y;
    int q0 = blockIdx.x * 64;
    int t  = threadIdx.x;
    int r  = t >> 2;
    int g  = t & 3;

    // stage Q tile into smem (coalesced), then lift this thread's row into regs
    {
        int rr = t >> 4;
        int dd = (t & 15) << 2;
#pragma unroll
        for (int p = 0; p < 4; p++) {
            int row = rr + p * 16;
            *(float4*)&QP[row * 68 + dd] =
                *(const float4*)(g_qkv + (size_t)(q0 + row) * QKVN + h * 192 + dd);
        }
    }
    __syncthreads();

    float4 q[16];
#pragma unroll
    for (int i = 0; i < 16; i++) q[i] = *(const float4*)&QP[r * 68 + i * 4];

    float m = -1e30f, l = 0.f;
    float4 acc[4];
#pragma unroll
    for (int i = 0; i < 4; i++) acc[i] = make_float4(0.f, 0.f, 0.f, 0.f);

    for (int kt = 0; kt < SEQ; kt += 64) {
        __syncthreads();   // previous iteration's P/V readers done
        {
            int rr = t >> 4;
            int dd = (t & 15) << 2;
#pragma unroll
            for (int p = 0; p < 4; p++) {
                int row = rr + p * 16;
                size_t base = (size_t)(kt + row) * QKVN + h * 192;
                *(float4*)&Ks[row * 64 + dd] = *(const float4*)(g_qkv + base + 64 + dd);
                *(float4*)&Vs[row * 64 + dd] = *(const float4*)(g_qkv + base + 128 + dd);
            }
        }
        __syncthreads();

        // logits for this thread's 16 columns
        float lg[16];
#pragma unroll
        for (int c = 0; c < 16; c++) {
            int cc = g * 16 + c;
            float s = 0.f;
#pragma unroll
            for (int d = 0; d < 16; d++) {
                float4 kv = *(const float4*)&Ks[cc * 64 + d * 4];
                s = fmaf(q[d].x, kv.x, s);
                s = fmaf(q[d].y, kv.y, s);
                s = fmaf(q[d].z, kv.z, s);
                s = fmaf(q[d].w, kv.w, s);
            }
            lg[c] = s * 0.125f;   // 1/sqrt(64)
        }

        // row max across the 4 threads of this row
        float tm = lg[0];
#pragma unroll
        for (int c = 1; c < 16; c++) tm = fmaxf(tm, lg[c]);
        tm = fmaxf(tm, __shfl_xor_sync(0xffffffffu, tm, 1));
        tm = fmaxf(tm, __shfl_xor_sync(0xffffffffu, tm, 2));

        float mn   = fmaxf(m, tm);
        float corr = __expf(m - mn);
        m = mn;
        l *= corr;
#pragma unroll
        for (int i = 0; i < 4; i++) {
            acc[i].x *= corr; acc[i].y *= corr;
            acc[i].z *= corr; acc[i].w *= corr;
        }

        float ps = 0.f;
#pragma unroll
        for (int c = 0; c < 16; c++) {
            float p = __expf(lg[c] - mn);
            ps += p;
            QP[r * 68 + g * 16 + c] = p;
        }
        ps += __shfl_xor_sync(0xffffffffu, ps, 1);
        ps += __shfl_xor_sync(0xffffffffu, ps, 2);
        l += ps;
        __syncthreads();   // P tile complete

        // PV accumulate: out[r][g*16+d] += sum_k P[r][k] * V[k][g*16+d]
#pragma unroll 4
        for (int k = 0; k < 64; k++) {
            float p = QP[r * 68 + k];
#pragma unroll
            for (int d4 = 0; d4 < 4; d4++) {
                float4 v = *(const float4*)&Vs[k * 64 + g * 16 + d4 * 4];
                acc[d4].x = fmaf(p, v.x, acc[d4].x);
                acc[d4].y = fmaf(p, v.y, acc[d4].y);
                acc[d4].z = fmaf(p, v.z, acc[d4].z);
                acc[d4].w = fmaf(p, v.w, acc[d4].w);
            }
        }
    }

    float inv = 1.f / l;
    float* outp = g_att + (size_t)(q0 + r) * EMB + h * HD + g * 16;
#pragma unroll
    for (int d4 = 0; d4 < 4; d4++) {
        float4 v = acc[d4];
        v.x *= inv; v.y *= inv; v.z *= inv; v.w *= inv;
        *(float4*)(outp + d4 * 4) = v;
    }
}

static const int ATTN_SMEM = (64 * 68 + 2 * 64 * 64) * (int)sizeof(float); // 50176

extern "C" void kernel_launch(void* const* d_in, const int* in_sizes, int n_in,
                              void* d_out, int out_size)
{
    (void)in_sizes; (void)n_in; (void)out_size;
    const float* x    = (const float*)d_in[0];
    const float* Wqkv = (const float*)d_in[1];
    const float* bqkv = (const float*)d_in[2];
    const float* Wo   = (const float*)d_in[3];
    const float* bo   = (const float*)d_in[4];
    float* out = (float*)d_out;

    float *qkv, *att;
    cudaGetSymbolAddress((void**)&qkv, g_qkv);
    cudaGetSymbolAddress((void**)&att, g_att);

    cudaFuncSetAttribute(attn_kernel,
                         cudaFuncAttributeMaxDynamicSharedMemorySize, ATTN_SMEM);

    // 1) qkv = x @ Wqkv^T + bqkv
    dim3 g1(QKVN / 128, SEQ / 128);
    sgemm_bias<<<g1, 256>>>(x, Wqkv, bqkv, qkv, SEQ, QKVN, EMB);

    // 2) per-head attention -> g_att [S, E]
    dim3 g2(SEQ / 64, NH);
    attn_kernel<<<g2, 256, ATTN_SMEM>>>();

    // 3) out = att @ Wo^T + bo
    dim3 g3(EMB / 128, SEQ / 128);
    sgemm_bias<<<g3, 256>>>(att, Wo, bo, out, SEQ, EMB, EMB);
}

// round 2
// speedup vs baseline: 4.1550x; 4.1550x over previous
#include <cuda_runtime.h>

#define SEQ 4096
#define EMB 1024
#define NH  16
#define HD  64
#define QKVN (3*EMB)

// Scratch (no cudaMalloc allowed): qkv projection [S, 3E], attention output [S, E]
__device__ float g_qkv[(size_t)SEQ * QKVN];
__device__ float g_att[(size_t)SEQ * EMB];

// ---------------------------------------------------------------------------
// SGEMM: C[M,N] = A[M,K] @ B[N,K]^T + bias[N]
// 128x128 block tile, BK=16, 256 threads, 8x8 register micro-tile.
// ---------------------------------------------------------------------------
__global__ __launch_bounds__(256)
void sgemm_bias(const float* __restrict__ A, const float* __restrict__ B,
                const float* __restrict__ bias, float* __restrict__ C,
                int M, int N, int K)
{
    const int BK = 16;
    __shared__ float As[16][132];
    __shared__ float Bs[16][132];

    int t  = threadIdx.x;
    int tx = t & 15;
    int ty = t >> 4;
    int bm = blockIdx.y * 128;
    int bn = blockIdx.x * 128;

    const float* Ab = A + (size_t)bm * K;
    const float* Bb = B + (size_t)bn * K;

    int lm = t >> 2;
    int lk = (t & 3) << 2;

    float acc[8][8];
#pragma unroll
    for (int i = 0; i < 8; i++)
#pragma unroll
        for (int j = 0; j < 8; j++) acc[i][j] = 0.f;

    for (int k0 = 0; k0 < K; k0 += BK) {
#pragma unroll
        for (int p = 0; p < 2; p++) {
            int m = lm + p * 64;
            float4 va = *(const float4*)(Ab + (size_t)m * K + k0 + lk);
            As[lk + 0][m] = va.x; As[lk + 1][m] = va.y;
            As[lk + 2][m] = va.z; As[lk + 3][m] = va.w;
            float4 vb = *(const float4*)(Bb + (size_t)m * K + k0 + lk);
            Bs[lk + 0][m] = vb.x; Bs[lk + 1][m] = vb.y;
            Bs[lk + 2][m] = vb.z; Bs[lk + 3][m] = vb.w;
        }
        __syncthreads();

#pragma unroll
        for (int k = 0; k < BK; k++) {
            float a[8], b[8];
            *(float4*)&a[0] = *(const float4*)&As[k][ty * 8];
            *(float4*)&a[4] = *(const float4*)&As[k][ty * 8 + 4];
            *(float4*)&b[0] = *(const float4*)&Bs[k][tx * 8];
            *(float4*)&b[4] = *(const float4*)&Bs[k][tx * 8 + 4];
#pragma unroll
            for (int i = 0; i < 8; i++)
#pragma unroll
                for (int j = 0; j < 8; j++)
                    acc[i][j] = fmaf(a[i], b[j], acc[i][j]);
        }
        __syncthreads();
    }

#pragma unroll
    for (int i = 0; i < 8; i++) {
        int m = bm + ty * 8 + i;
        float* Crow = C + (size_t)m * N + bn + tx * 8;
        const float* brow = bias + bn + tx * 8;
#pragma unroll
        for (int j = 0; j < 8; j += 4) {
            float4 v;
            v.x = acc[i][j + 0] + brow[j + 0];
            v.y = acc[i][j + 1] + brow[j + 1];
            v.z = acc[i][j + 2] + brow[j + 2];
            v.w = acc[i][j + 3] + brow[j + 3];
            *(float4*)(Crow + j) = v;
        }
    }
}

// ---------------------------------------------------------------------------
// Flash attention, GEMM-structured.
// CTA: 128 query rows x 1 head. 256 threads as 16x16 grid.
// QK^T: 8x8 micro-tile per thread (inner dim 64).
// PV:   8 rows x 4 dims per thread (inner dim 128), k unrolled by 4.
// smem: Q^T[64][132], K^T[64][132], V[128][68], P[128][132]  (~166 KB)
// ---------------------------------------------------------------------------
#define BQ 128
#define BKEY 128

__global__ __launch_bounds__(256)
void attn_kernel()
{
    extern __shared__ float sm[];
    float* Qs = sm;                    // [64][132] transposed (d-major)
    float* Ks = Qs + 64 * 132;         // [64][132] transposed
    float* Vs = Ks + 64 * 132;         // [128][68] k-major
    float* Ps = Vs + 128 * 68;         // [128][132] row-major probs

    int h  = blockIdx.y;
    int q0 = blockIdx.x * BQ;
    int t  = threadIdx.x;
    int tx = t & 15;
    int ty = t >> 4;

    // ---- load Q tile transposed into smem ----
    {
        int row = t >> 1;
        int dbase = (t & 1) * 32;
        const float* src = g_qkv + (size_t)(q0 + row) * QKVN + h * 192 + dbase;
#pragma unroll
        for (int c = 0; c < 8; c++) {
            float4 v = *(const float4*)(src + c * 4);
            int d = dbase + c * 4;
            Qs[(d + 0) * 132 + row] = v.x;
            Qs[(d + 1) * 132 + row] = v.y;
            Qs[(d + 2) * 132 + row] = v.z;
            Qs[(d + 3) * 132 + row] = v.w;
        }
    }

    float m_run[8], l_run[8];
    float4 oacc[8];
#pragma unroll
    for (int i = 0; i < 8; i++) {
        m_run[i] = -1e30f;
        l_run[i] = 0.f;
        oacc[i] = make_float4(0.f, 0.f, 0.f, 0.f);
    }

    for (int kt = 0; kt < SEQ; kt += BKEY) {
        __syncthreads();   // previous tile's consumers done

        // ---- load K (transposed) and V (k-major) tiles ----
        {
            int row = t >> 1;
            int dbase = (t & 1) * 32;
            const float* kp = g_qkv + (size_t)(kt + row) * QKVN + h * 192 + 64 + dbase;
#pragma unroll
            for (int c = 0; c < 8; c++) {
                float4 v = *(const float4*)(kp + c * 4);
                int d = dbase + c * 4;
                Ks[(d + 0) * 132 + row] = v.x;
                Ks[(d + 1) * 132 + row] = v.y;
                Ks[(d + 2) * 132 + row] = v.z;
                Ks[(d + 3) * 132 + row] = v.w;
            }
            const float* vp = g_qkv + (size_t)(kt + row) * QKVN + h * 192 + 128 + dbase;
#pragma unroll
            for (int c = 0; c < 8; c++) {
                *(float4*)&Vs[row * 68 + dbase + c * 4] = *(const float4*)(vp + c * 4);
            }
        }
        __syncthreads();

        // ---- logits: acc[8][8] = Q_tile @ K_tile^T ----
        float acc[8][8];
#pragma unroll
        for (int i = 0; i < 8; i++)
#pragma unroll
            for (int j = 0; j < 8; j++) acc[i][j] = 0.f;

#pragma unroll 4
        for (int k = 0; k < HD; k++) {
            float a[8], b[8];
            *(float4*)&a[0] = *(const float4*)&Qs[k * 132 + ty * 8];
            *(float4*)&a[4] = *(const float4*)&Qs[k * 132 + ty * 8 + 4];
            *(float4*)&b[0] = *(const float4*)&Ks[k * 132 + tx * 8];
            *(float4*)&b[4] = *(const float4*)&Ks[k * 132 + tx * 8 + 4];
#pragma unroll
            for (int i = 0; i < 8; i++)
#pragma unroll
                for (int j = 0; j < 8; j++)
                    acc[i][j] = fmaf(a[i], b[j], acc[i][j]);
        }

        // ---- online softmax (per row, reduced over 16 tx lanes) ----
#pragma unroll
        for (int i = 0; i < 8; i++) {
#pragma unroll
            for (int j = 0; j < 8; j++) acc[i][j] *= 0.125f;  // 1/sqrt(64)

            float tm = acc[i][0];
#pragma unroll
            for (int j = 1; j < 8; j++) tm = fmaxf(tm, acc[i][j]);
            tm = fmaxf(tm, __shfl_xor_sync(0xffffffffu, tm, 1));
            tm = fmaxf(tm, __shfl_xor_sync(0xffffffffu, tm, 2));
            tm = fmaxf(tm, __shfl_xor_sync(0xffffffffu, tm, 4));
            tm = fmaxf(tm, __shfl_xor_sync(0xffffffffu, tm, 8));

            float mn = fmaxf(m_run[i], tm);
            float corr = __expf(m_run[i] - mn);
            m_run[i] = mn;
            l_run[i] *= corr;
            oacc[i].x *= corr; oacc[i].y *= corr;
            oacc[i].z *= corr; oacc[i].w *= corr;

            float s = 0.f;
#pragma unroll
            for (int j = 0; j < 8; j++) {
                float p = __expf(acc[i][j] - mn);
                s += p;
                acc[i][j] = p;
            }
            s += __shfl_xor_sync(0xffffffffu, s, 1);
            s += __shfl_xor_sync(0xffffffffu, s, 2);
            s += __shfl_xor_sync(0xffffffffu, s, 4);
            s += __shfl_xor_sync(0xffffffffu, s, 8);
            l_run[i] += s;

            *(float4*)&Ps[(ty * 8 + i) * 132 + tx * 8]     = *(float4*)&acc[i][0];
            *(float4*)&Ps[(ty * 8 + i) * 132 + tx * 8 + 4] = *(float4*)&acc[i][4];
        }
        __syncthreads();   // P tile complete

        // ---- PV: oacc[8][4] += P[rows][k] @ V[k][dims] ----
#pragma unroll 2
        for (int k = 0; k < BKEY; k += 4) {
            float4 b0 = *(const float4*)&Vs[(k + 0) * 68 + tx * 4];
            float4 b1 = *(const float4*)&Vs[(k + 1) * 68 + tx * 4];
            float4 b2 = *(const float4*)&Vs[(k + 2) * 68 + tx * 4];
            float4 b3 = *(const float4*)&Vs[(k + 3) * 68 + tx * 4];
#pragma unroll
            for (int i = 0; i < 8; i++) {
                float4 p4 = *(const float4*)&Ps[(ty * 8 + i) * 132 + k];
                oacc[i].x = fmaf(p4.x, b0.x, oacc[i].x);
                oacc[i].y = fmaf(p4.x, b0.y, oacc[i].y);
                oacc[i].z = fmaf(p4.x, b0.z, oacc[i].z);
                oacc[i].w = fmaf(p4.x, b0.w, oacc[i].w);
                oacc[i].x = fmaf(p4.y, b1.x, oacc[i].x);
                oacc[i].y = fmaf(p4.y, b1.y, oacc[i].y);
                oacc[i].z = fmaf(p4.y, b1.z, oacc[i].z);
                oacc[i].w = fmaf(p4.y, b1.w, oacc[i].w);
                oacc[i].x = fmaf(p4.z, b2.x, oacc[i].x);
                oacc[i].y = fmaf(p4.z, b2.y, oacc[i].y);
                oacc[i].z = fmaf(p4.z, b2.z, oacc[i].z);
                oacc[i].w = fmaf(p4.z, b2.w, oacc[i].w);
                oacc[i].x = fmaf(p4.w, b3.x, oacc[i].x);
                oacc[i].y = fmaf(p4.w, b3.y, oacc[i].y);
                oacc[i].z = fmaf(p4.w, b3.z, oacc[i].z);
                oacc[i].w = fmaf(p4.w, b3.w, oacc[i].w);
            }
        }
    }

    // ---- normalize and write out ----
#pragma unroll
    for (int i = 0; i < 8; i++) {
        float inv = 1.f / l_run[i];
        float4 v = oacc[i];
        v.x *= inv; v.y *= inv; v.z *= inv; v.w *= inv;
        *(float4*)(g_att + (size_t)(q0 + ty * 8 + i) * EMB + h * HD + tx * 4) = v;
    }
}

static const int ATTN_SMEM = (64 * 132 + 64 * 132 + 128 * 68 + 128 * 132) * (int)sizeof(float);

extern "C" void kernel_launch(void* const* d_in, const int* in_sizes, int n_in,
                              void* d_out, int out_size)
{
    (void)in_sizes; (void)n_in; (void)out_size;
    const float* x    = (const float*)d_in[0];
    const float* Wqkv = (const float*)d_in[1];
    const float* bqkv = (const float*)d_in[2];
    const float* Wo   = (const float*)d_in[3];
    const float* bo   = (const float*)d_in[4];
    float* out = (float*)d_out;

    float *qkv, *att;
    cudaGetSymbolAddress((void**)&qkv, g_qkv);
    cudaGetSymbolAddress((void**)&att, g_att);

    cudaFuncSetAttribute(attn_kernel,
                         cudaFuncAttributeMaxDynamicSharedMemorySize, ATTN_SMEM);

    // 1) qkv = x @ Wqkv^T + bqkv
    dim3 g1(QKVN / 128, SEQ / 128);
    sgemm_bias<<<g1, 256>>>(x, Wqkv, bqkv, qkv, SEQ, QKVN, EMB);

    // 2) per-head attention -> g_att [S, E]
    dim3 g2(SEQ / BQ, NH);
    attn_kernel<<<g2, 256, ATTN_SMEM>>>();

    // 3) out = att @ Wo^T + bo
    dim3 g3(EMB / 128, SEQ / 128);
    sgemm_bias<<<g3, 256>>>(att, Wo, bo, out, SEQ, EMB, EMB);
}